// round 2
// baseline (speedup 1.0000x reference)
#include <cuda_runtime.h>
#include <cuda_bf16.h>
#include <math.h>

// Problem dims (fixed by the dataset)
#define HH 768
#define G3 2304          // 3*H
#define BB 64            // batch
#define LL 512           // seq len
#define NSTEP 513        // 512 sequence steps + 1 final (end-token) step
#define NROWS (NSTEP*BB) // 32832

#define NBLK 144         // persistent blocks (<=148 SMs -> co-resident)
#define TPB  256
#define NCOL 16          // G3 / NBLK
#define CHUNK 256        // k-chunk staged in smem (768 = 3*256)

// Scratch (device globals — allocation-free rule)
static __device__ __align__(256) float g_gi[(size_t)NROWS * G3];   // precomputed input gates
static __device__ __align__(256) float g_gh[BB * G3];              // recurrent gate pre-activations
static __device__ __align__(256) float g_hT[HH * BB];              // h transposed [k][b] for gemm staging
static __device__ __align__(256) float g_hbm[BB * HH];             // h [b][k] for gates/scorer
static __device__ unsigned g_count = 0;                            // monotonic barrier counter
static __device__ unsigned g_gen   = 0;                            // monotonic generation

// ---------------------------------------------------------------------------
__global__ void k_init()
{
    int t = blockIdx.x * blockDim.x + threadIdx.x;
    if (t < BB * HH) { g_hT[t] = 0.f; g_hbm[t] = 0.f; }
}

// ---------------------------------------------------------------------------
// gi[l*64+b, n] = relu_if_seq(emb[token(b,l)]) . w_ih[n,:] + b_ih[n]
// Block tile 64x64, BK=16, 64 threads, 8x8 register tiles.
__global__ void k_gi(const int* __restrict__ goal, const float* __restrict__ emb,
                     const float* __restrict__ w_ih, const float* __restrict__ b_ih)
{
    __shared__ __align__(16) float As[16][64];
    __shared__ __align__(16) float Bs[16][64];
    __shared__ int tok[64];

    const int by  = blockIdx.y;        // step index
    const int n0  = blockIdx.x * 64;   // output-col base
    const int tid = threadIdx.x;       // 64 threads
    const bool seq = (by < LL);

    tok[tid] = seq ? goal[tid * LL + by] : 1;   // goal_batch is [B, L]
    __syncthreads();

    const int mg = (tid >> 3) * 8;
    const int ng = (tid & 7) * 8;

    float acc[8][8];
#pragma unroll
    for (int i = 0; i < 8; i++)
#pragma unroll
        for (int j = 0; j < 8; j++) acc[i][j] = 0.f;

    for (int k0 = 0; k0 < HH; k0 += 16) {
#pragma unroll
        for (int j = 0; j < 4; j++) {
            int f  = tid + 64 * j;   // 0..255
            int r  = f >> 2;         // tile row 0..63
            int kk = (f & 3) * 4;    // k offset 0,4,8,12
            float4 v = *(const float4*)(emb + (size_t)tok[r] * HH + k0 + kk);
            if (seq) { v.x = fmaxf(v.x, 0.f); v.y = fmaxf(v.y, 0.f);
                       v.z = fmaxf(v.z, 0.f); v.w = fmaxf(v.w, 0.f); }
            As[kk][r] = v.x; As[kk+1][r] = v.y; As[kk+2][r] = v.z; As[kk+3][r] = v.w;
            float4 w = *(const float4*)(w_ih + (size_t)(n0 + r) * HH + k0 + kk);
            Bs[kk][r] = w.x; Bs[kk+1][r] = w.y; Bs[kk+2][r] = w.z; Bs[kk+3][r] = w.w;
        }
        __syncthreads();
#pragma unroll
        for (int k = 0; k < 16; k++) {
            float4 a0 = *(const float4*)&As[k][mg];
            float4 a1 = *(const float4*)&As[k][mg + 4];
            float4 b0 = *(const float4*)&Bs[k][ng];
            float4 b1 = *(const float4*)&Bs[k][ng + 4];
            float av[8] = {a0.x, a0.y, a0.z, a0.w, a1.x, a1.y, a1.z, a1.w};
            float bv[8] = {b0.x, b0.y, b0.z, b0.w, b1.x, b1.y, b1.z, b1.w};
#pragma unroll
            for (int i = 0; i < 8; i++)
#pragma unroll
                for (int j = 0; j < 8; j++) acc[i][j] += av[i] * bv[j];
        }
        __syncthreads();
    }

    const int rowBase = by * BB;
#pragma unroll
    for (int i = 0; i < 8; i++) {
        float* dst = g_gi + (size_t)(rowBase + mg + i) * G3 + n0 + ng;
#pragma unroll
        for (int j = 0; j < 8; j++) dst[j] = acc[i][j] + b_ih[n0 + ng + j];
    }
}

// ---------------------------------------------------------------------------
// software grid barrier: monotonic counter/generation (no reset race,
// survives graph replays because everything is relative)
__device__ __forceinline__ void gsync()
{
    __threadfence();
    __syncthreads();
    if (threadIdx.x == 0) {
        unsigned old = atomicAdd(&g_count, 1u) + 1u;
        if (old % NBLK == 0u) {
            atomicAdd(&g_gen, 1u);
        } else {
            unsigned target = (old + NBLK - 1u) / NBLK;
            volatile unsigned* vg = &g_gen;
            while (*vg < target) __nanosleep(32);
        }
    }
    __syncthreads();
}

__device__ __forceinline__ float sigmoidf_(float x)
{
    return 1.f / (1.f + __expf(-x));
}

// ---------------------------------------------------------------------------
// Persistent recurrence: 513 GRU steps. 144 blocks x 256 threads.
// Each block owns 16 output cols of gh; w_hh slice lives in smem for the
// whole kernel. h is staged per-step from g_hT (transposed) chunks.
// dyn smem: ws[768][16] (48KB) + hs[256][64] (64KB) = 112KB
__global__ void __launch_bounds__(TPB, 1) k_rec(const float* __restrict__ w_hh,
                                                const float* __restrict__ b_hh)
{
    extern __shared__ float smem[];
    float* ws = smem;                 // [768][16]
    float* hs = smem + HH * NCOL;     // [256][64], reused as reduce buf

    const int tid  = threadIdx.x;
    const int n0   = blockIdx.x * NCOL;
    const int ks   = tid >> 5;        // 0..7 k-split (== warp id)
    const int slot = tid & 31;
    const int rg   = slot & 7;        // row group: rows rg*8..rg*8+7
    const int cg   = slot >> 3;       // col group: cols cg*4..cg*4+3

    // preload w slice once: ws[k][c] = w_hh[n0+c][k]
    for (int idx = tid; idx < NCOL * HH; idx += TPB) {
        int c = idx / HH;
        int k = idx - c * HH;
        ws[k * NCOL + c] = w_hh[(size_t)(n0 + c) * HH + k];
    }
    __syncthreads();

    const int gtid = blockIdx.x * TPB + tid;   // 0..36863

    for (int l = 0; l < NSTEP; l++) {
        // ---- gemm phase: gh[0:64][n0:n0+16] = h @ w_hh_slice^T ----
        float acc[8][4];
#pragma unroll
        for (int i = 0; i < 8; i++)
#pragma unroll
            for (int j = 0; j < 4; j++) acc[i][j] = 0.f;

        for (int ch = 0; ch < HH / CHUNK; ch++) {
            __syncthreads();   // hs free (prev chunk / prev reduction done)
            {
                const float4* src = (const float4*)(g_hT + (size_t)ch * CHUNK * BB);
                float4* dst = (float4*)hs;
                for (int i = tid; i < CHUNK * BB / 4; i += TPB)
                    dst[i] = __ldcg(src + i);
            }
            __syncthreads();

            const int kb = ks * 32;
#pragma unroll 8
            for (int k = 0; k < 32; k++) {
                const int kk = kb + k;
                float4 w  = *(const float4*)&ws[(ch * CHUNK + kk) * NCOL + cg * 4];
                float4 h0 = *(const float4*)&hs[kk * BB + rg * 8];
                float4 h1 = *(const float4*)&hs[kk * BB + rg * 8 + 4];
                float hv[8] = {h0.x, h0.y, h0.z, h0.w, h1.x, h1.y, h1.z, h1.w};
                float wv[4] = {w.x, w.y, w.z, w.w};
#pragma unroll
                for (int i = 0; i < 8; i++)
#pragma unroll
                    for (int j = 0; j < 4; j++) acc[i][j] += hv[i] * wv[j];
            }
        }

        // ---- k-split reduction via smem (reuse hs as float4[8][256]) ----
        __syncthreads();
        float4* red = (float4*)hs;
#pragma unroll
        for (int r = 0; r < 8; r++)
            red[r * 256 + tid] = make_float4(acc[r][0], acc[r][1], acc[r][2], acc[r][3]);
        __syncthreads();
        {
            const int r  = tid >> 5;        // 0..7
            const int sp = tid & 31;        // slot' = rg + cg*8
            float4 s = red[r * 256 + sp];
#pragma unroll
            for (int k2 = 1; k2 < 8; k2++) {
                float4 v = red[r * 256 + k2 * 32 + sp];
                s.x += v.x; s.y += v.y; s.z += v.z; s.w += v.w;
            }
            const int m    = (sp & 7) * 8 + r;
            const int col0 = n0 + (sp >> 3) * 4;
            __stcg((float4*)(g_gh + (size_t)m * G3 + col0), s);
        }

        gsync();

        // ---- gate phase: 64*768 outputs over 36864 threads ----
        for (int t = gtid; t < BB * HH; t += NBLK * TPB) {
            const int b = t / HH;
            const int j = t - b * HH;
            const float* ghp = g_gh + (size_t)b * G3;
            float ghr = __ldcg(ghp + j);
            float ghz = __ldcg(ghp + j + HH);
            float ghn = __ldcg(ghp + j + 2 * HH);
            const float* gi = g_gi + ((size_t)l * BB + b) * G3;
            float r = sigmoidf_(gi[j]      + ghr + b_hh[j]);
            float z = sigmoidf_(gi[j + HH] + ghz + b_hh[j + HH]);
            float n = tanhf(gi[j + 2 * HH] + r * (ghn + b_hh[j + 2 * HH]));
            float hold = __ldcg(&g_hbm[t]);
            float h = (1.f - z) * n + z * hold;
            if (l < LL) h = fmaxf(h, 0.f);   // final step NOT relu'd
            __stcg(&g_hbm[t], h);
            __stcg(&g_hT[j * BB + b], h);
        }

        gsync();
    }
}

// ---------------------------------------------------------------------------
// Scorer MLP: y=relu(f@sw0.T+sb0); y=relu(y@sw1.T+sb1); out=y@swo.T+sbo
__global__ void k_score(const float* __restrict__ sw0, const float* __restrict__ sb0,
                        const float* __restrict__ sw1, const float* __restrict__ sb1,
                        const float* __restrict__ swo, const float* __restrict__ sbo,
                        float* __restrict__ out)
{
    __shared__ float xa[HH], xb[HH];
    __shared__ float red[256];
    const int b = blockIdx.x, tid = threadIdx.x;
    const float* hf = g_hbm + b * HH;

    for (int i = tid; i < HH; i += 256) xa[i] = hf[i];
    __syncthreads();

    for (int o = tid; o < HH; o += 256) {
        const float* w = sw0 + (size_t)o * HH;
        float s0 = 0, s1 = 0, s2 = 0, s3 = 0;
        for (int k = 0; k < HH; k += 4) {
            float4 wv = *(const float4*)(w + k);
            s0 += xa[k] * wv.x; s1 += xa[k+1] * wv.y;
            s2 += xa[k+2] * wv.z; s3 += xa[k+3] * wv.w;
        }
        xb[o] = fmaxf(s0 + s1 + s2 + s3 + sb0[o], 0.f);
    }
    __syncthreads();

    for (int o = tid; o < HH; o += 256) {
        const float* w = sw1 + (size_t)o * HH;
        float s0 = 0, s1 = 0, s2 = 0, s3 = 0;
        for (int k = 0; k < HH; k += 4) {
            float4 wv = *(const float4*)(w + k);
            s0 += xb[k] * wv.x; s1 += xb[k+1] * wv.y;
            s2 += xb[k+2] * wv.z; s3 += xb[k+3] * wv.w;
        }
        xa[o] = fmaxf(s0 + s1 + s2 + s3 + sb1[o], 0.f);
    }
    __syncthreads();

    float s = 0.f;
    for (int k = tid; k < HH; k += 256) s += xa[k] * swo[k];
    red[tid] = s;
    __syncthreads();
    for (int off = 128; off; off >>= 1) {
        if (tid < off) red[tid] += red[tid + off];
        __syncthreads();
    }
    if (tid == 0) out[b] = red[0] + sbo[0];
}

// ---------------------------------------------------------------------------
extern "C" void kernel_launch(void* const* d_in, const int* in_sizes, int n_in,
                              void* d_out, int out_size)
{
    const int*   goal = (const int*)  d_in[0];
    const float* emb  = (const float*)d_in[1];
    const float* w_ih = (const float*)d_in[2];
    const float* w_hh = (const float*)d_in[3];
    const float* b_ih = (const float*)d_in[4];
    const float* b_hh = (const float*)d_in[5];
    const float* sw0  = (const float*)d_in[6];
    const float* sb0  = (const float*)d_in[7];
    const float* sw1  = (const float*)d_in[8];
    const float* sb1  = (const float*)d_in[9];
    const float* swo  = (const float*)d_in[10];
    const float* sbo  = (const float*)d_in[11];
    float* out = (float*)d_out;

    const int smem_rec = (HH * NCOL + CHUNK * BB) * (int)sizeof(float); // 112KB
    cudaFuncSetAttribute(k_rec, cudaFuncAttributeMaxDynamicSharedMemorySize, smem_rec);

    k_init<<<(BB * HH + 255) / 256, 256>>>();
    k_gi<<<dim3(G3 / 64, NSTEP), 64>>>(goal, emb, w_ih, b_ih);
    k_rec<<<NBLK, TPB, smem_rec>>>(w_hh, b_hh);
    k_score<<<BB, 256>>>(sw0, sb0, sw1, sb1, swo, sbo, out);
}